// round 17
// baseline (speedup 1.0000x reference)
#include <cuda_runtime.h>
#include <cuda_fp16.h>
#include <cstdint>

// Problem dims (fixed by the dataset)
#define NROWS 65536
#define SDIM  128
#define DIN   512
#define HDIM  1024
#define DOUT  256

// ---------------------------------------------------------------------------
// Scratch (device globals; no allocation allowed)
// ---------------------------------------------------------------------------
__device__ float g_v[NROWS];        // v_i = Uhat_i . w_deep (excl. c)
__device__ float g_u[HDIM];         // u = W2 @ w_deep
__device__ float g_c;               // c = b2 . w_deep
__device__ float g_G[SDIM * SDIM];  // Gram = X^T X
__device__ float g_t[SDIM];         // t = X^T (v + c)
__device__ float g_w[SDIM];         // w = w_struct - G^{-1} t

// fp16 copies for tensor-core GEMMs (d1 is now consumed as fp32 directly)
__device__ __align__(16) __half g_W1t[HDIM * DIN];            // B^T [N,K], 1MB
__device__ __align__(16) __half g_Xt[(size_t)SDIM * NROWS];   // X^T, 16MB

// ---------------------------------------------------------------------------
// Helpers
// ---------------------------------------------------------------------------
__device__ __forceinline__ uint32_t smem_u32(const void* p) {
    uint32_t a;
    asm("{ .reg .u64 t; cvta.to.shared.u64 t, %1; cvt.u32.u64 %0, t; }"
        : "=r"(a) : "l"(p));
    return a;
}

#define CP16(sa, ga) \
    asm volatile("cp.async.cg.shared.global [%0], [%1], 16;" ::"r"(sa), "l"(ga) : "memory")
#define CP_COMMIT() asm volatile("cp.async.commit_group;" ::: "memory")
#define CP_WAIT1() asm volatile("cp.async.wait_group 1;" ::: "memory")

// m16n8k16 row.col fp16 MMA, fp32 accum (sm_80+ baseline -> legal on sm_103)
#define MMA4(d, a0, a1, a2, a3, b0, b1)                                     \
    asm volatile(                                                           \
        "mma.sync.aligned.m16n8k16.row.col.f32.f16.f16.f32 "                \
        "{%0,%1,%2,%3}, {%4,%5,%6,%7}, {%8,%9}, {%0,%1,%2,%3};"             \
        : "+f"((d)[0]), "+f"((d)[1]), "+f"((d)[2]), "+f"((d)[3])            \
        : "r"(a0), "r"(a1), "r"(a2), "r"(a3), "r"(b0), "r"(b1))

#define LDSM4(r, a)                                                         \
    asm volatile(                                                           \
        "ldmatrix.sync.aligned.m8n8.x4.shared.b16 {%0,%1,%2,%3}, [%4];"     \
        : "=r"((r)[0]), "=r"((r)[1]), "=r"((r)[2]), "=r"((r)[3])            \
        : "r"(a))

__device__ __forceinline__ uint32_t packh2(float lo, float hi) {
    __half2 h = __floats2half2_rn(lo, hi);
    return *(uint32_t*)&h;
}

// ---------------------------------------------------------------------------
// Prep (merged): W1 transpose-convert, zero v/G/t, u = W2@w_deep, c = b2.w_deep
// <<<2048, 256>>>
// ---------------------------------------------------------------------------
__global__ void k_prep(const float* __restrict__ W1, const float* __restrict__ W2,
                       const float* __restrict__ b2, const float* __restrict__ w_deep) {
    int i = blockIdx.x * blockDim.x + threadIdx.x;  // 0..524287, exact for W1
    // W1 [DIN, HDIM] -> transposed fp16 [HDIM, DIN]
    {
        int k = i >> 10, n = i & (HDIM - 1);
        g_W1t[n * DIN + k] = __float2half_rn(W1[i]);
    }
    if (i < NROWS) g_v[i] = 0.f;
    if (i < SDIM * SDIM) g_G[i] = 0.f;
    if (i < SDIM) g_t[i] = 0.f;
    if (i < HDIM) {  // u
        const float* r = &W2[(size_t)i * DOUT];
        float s = 0.f;
#pragma unroll 4
        for (int k = 0; k < DOUT; k++) s += r[k] * w_deep[k];
        g_u[i] = s;
    }
    if (blockIdx.x == 4 && threadIdx.x < 32) {  // c
        int lane = threadIdx.x;
        float s = 0.f;
#pragma unroll
        for (int e = 0; e < 8; e++) s += b2[lane + 32 * e] * w_deep[lane + 32 * e];
#pragma unroll
        for (int o = 16; o > 0; o >>= 1) s += __shfl_down_sync(0xffffffffu, s, o);
        if (lane == 0) g_c = s;
    }
}

// X [NROWS,128] fp32 -> Xt [128,NROWS] fp16 (tiled transpose)
__global__ void k_conv_Xt(const float* __restrict__ X) {
    __shared__ float tile[32][33];
    int tx = threadIdx.x, ty = threadIdx.y;          // (32,8)
    int r0 = blockIdx.x * 32, c0 = blockIdx.y * 32;  // grid (2048,4)
#pragma unroll
    for (int i = 0; i < 4; i++)
        tile[ty + i * 8][tx] = X[(size_t)(r0 + ty + i * 8) * SDIM + c0 + tx];
    __syncthreads();
#pragma unroll
    for (int i = 0; i < 4; i++)
        g_Xt[(size_t)(c0 + ty + i * 8) * NROWS + r0 + tx] =
            __float2half_rn(tile[tx][ty + i * 8]);
}

// ---------------------------------------------------------------------------
// Tensor-core fused MLP via fp16 mma.sync; A consumed directly as fp32:
//   v_i += sum_j relu((d1 @ W1)_ij + b1_j) * u_j
// C tile 128x128 per CTA (8 warps, 32x64 each). K chunks of 64, 2-stage
// cp.async pipeline. A staged as RAW FP32 (row stride 288B: 8g+2tg bank
// pattern -> conflict-free LDS.64), fragments built with cvt at use time.
// B staged fp16 with XOR swizzle + ldmatrix.x4. smem 107.5KB -> 2 CTAs/SM.
// ---------------------------------------------------------------------------
#define BKC     64
#define AROWB   288                       // 64 floats + 32B pad (stride/4≡8 mod 32)
#define ASTG    (128 * AROWB)             // 36864 B
#define BSTG    16384                     // 128 rows * 128B fp16
#define STAGEB  (ASTG + BSTG)             // 53248 B
#define NSTG    2
#define SMEM_MMA (1024 + NSTG * STAGEB)   // 107520 B

__global__ __launch_bounds__(256, 2) void k_mlp_mma(const float* __restrict__ d1,
                                                    const float* __restrict__ b1) {
    extern __shared__ char sm[];
    float* bs = (float*)sm;            // [128] b1 slice
    float* us = (float*)(sm + 512);    // [128] u slice
    char* tiles = sm + 1024;
    const uint32_t tilesU = smem_u32(tiles);

    const int tid = threadIdx.x, lane = tid & 31, wid = tid >> 5;
    const int wm = wid & 3, wn = wid >> 2;
    const int g = lane >> 2, tg = lane & 3;
    const int rowBase = blockIdx.y * 128, colBase = blockIdx.x * 128;

    if (tid < 128) {
        bs[tid] = b1[colBase + tid];
        us[tid] = g_u[colBase + tid];
    }

    const float* Ag = d1 + (size_t)rowBase * DIN;
    const __half* Bg = g_W1t + (size_t)colBase * DIN;

    // A fragment fp32 smem byte offsets (within a stage): rows for mt, +kk at use
    const int mrow = lane & 7, mat = lane >> 3;
    uint32_t aRow[2][2];  // [mt][0]=row g-group, [1]=+8 rows
#pragma unroll
    for (int mt = 0; mt < 2; mt++) {
        aRow[mt][0] = (uint32_t)((wm * 32 + mt * 16 + g) * AROWB + tg * 8);
        aRow[mt][1] = aRow[mt][0] + 8 * AROWB;
    }
    // B ldmatrix swizzled components
    uint32_t bBase[4], bX[4];
    const uint32_t bKs = (uint32_t)(mat & 1);
#pragma unroll
    for (int ntp = 0; ntp < 4; ntp++) {
        int n = wn * 64 + ntp * 16 + (mat >> 1) * 8 + mrow;
        bBase[ntp] = (uint32_t)(ASTG + n * 128);
        bX[ntp] = (uint32_t)(n & 7);
    }

    float acc[2][8][4] = {};

    auto load_stage = [&](int buf, int k0) {
        uint32_t sa = tilesU + buf * STAGEB;
        // A: 128 rows x 16 segs of 16B fp32 -> 8 per thread
#pragma unroll
        for (int l = 0; l < 8; l++) {
            int idx = tid + l * 256;          // 0..2047
            int r = idx >> 4, s = idx & 15;
            CP16(sa + (uint32_t)(r * AROWB + s * 16),
                 Ag + (size_t)r * DIN + k0 + s * 4);
        }
        // B: 128 rows x 8 segs of 16B fp16 -> 4 per thread (XOR swizzle)
        uint32_t sb = sa + ASTG;
#pragma unroll
        for (int l = 0; l < 4; l++) {
            int idx = tid + l * 256;
            int r = idx >> 3, s = idx & 7;
            CP16(sb + (uint32_t)(r * 128 + ((s ^ (r & 7)) << 4)),
                 Bg + (size_t)r * DIN + k0 + s * 8);
        }
    };

    auto compute_stage = [&](int buf) {
        const char* SA = tiles + buf * STAGEB;
        uint32_t base = tilesU + buf * STAGEB;
#pragma unroll
        for (uint32_t kk = 0; kk < 4; kk++) { // four k16 steps per BK=64 chunk
            uint32_t a[2][4];
#pragma unroll
            for (int mt = 0; mt < 2; mt++) {
                const char* p0 = SA + aRow[mt][0] + kk * 64;
                const char* p1 = SA + aRow[mt][1] + kk * 64;
                float2 q0 = *(const float2*)p0;
                float2 q1 = *(const float2*)p1;
                float2 q2 = *(const float2*)(p0 + 32);
                float2 q3 = *(const float2*)(p1 + 32);
                a[mt][0] = packh2(q0.x, q0.y);
                a[mt][1] = packh2(q1.x, q1.y);
                a[mt][2] = packh2(q2.x, q2.y);
                a[mt][3] = packh2(q3.x, q3.y);
            }
#pragma unroll
            for (int ntp = 0; ntp < 4; ntp++) {
                uint32_t b[4];
                LDSM4(b, base + bBase[ntp] + ((((kk << 1) | bKs) ^ bX[ntp]) << 4));
#pragma unroll
                for (int h = 0; h < 2; h++) {
                    int nt = ntp * 2 + h;
                    MMA4(acc[0][nt], a[0][0], a[0][1], a[0][2], a[0][3],
                         b[h * 2], b[h * 2 + 1]);
                    MMA4(acc[1][nt], a[1][0], a[1][1], a[1][2], a[1][3],
                         b[h * 2], b[h * 2 + 1]);
                }
            }
        }
    };

    load_stage(0, 0);
    CP_COMMIT();
    load_stage(1, BKC);
    CP_COMMIT();

#pragma unroll 1
    for (int c = 0; c < DIN / BKC; c++) {   // 8 chunks
        CP_WAIT1();                 // stage c resident
        __syncthreads();
        compute_stage(c & 1);
        __syncthreads();            // all warps done with stage c's buffers
        if (c + 2 < DIN / BKC) load_stage(c & 1, (c + 2) * BKC);
        CP_COMMIT();
    }

    // Epilogue: p(row) = sum_cols relu(acc + b1)*u, reduce quad, atomic to g_v
#pragma unroll
    for (int mt = 0; mt < 2; mt++) {
#pragma unroll
        for (int h = 0; h < 2; h++) {
            float p = 0.f;
#pragma unroll
            for (int nt = 0; nt < 8; nt++) {
                int c0 = wn * 64 + nt * 8 + tg * 2;
                p += fmaxf(acc[mt][nt][h * 2 + 0] + bs[c0], 0.f) * us[c0];
                p += fmaxf(acc[mt][nt][h * 2 + 1] + bs[c0 + 1], 0.f) * us[c0 + 1];
            }
            p += __shfl_xor_sync(0xffffffffu, p, 1);
            p += __shfl_xor_sync(0xffffffffu, p, 2);
            if (tg == 0)
                atomicAdd(&g_v[rowBase + wm * 32 + mt * 16 + h * 8 + g], p);
        }
    }
}

// ---------------------------------------------------------------------------
// Tensor-core Gram: G += Xt @ Xt^T (fp16 in, fp32 accum), t += Xt (v + c).
// 64 blocks, each 1024 K-rows in 16 chunks of 64. A and B fragments read
// the SAME swizzled smem tile (128 rows x 128B). 3-stage pipeline.
// ---------------------------------------------------------------------------
#define GKC     64
#define GTILE   16384
#define GNSTG   3
#define SMEM_GRAM (4096 + GNSTG * GTILE)    // 53248 B

__global__ __launch_bounds__(256) void k_gram_mma() {
    extern __shared__ char sm[];
    float* vs = (float*)sm;            // [1024] v + c
    const uint32_t tilesU = smem_u32(sm + 4096);

    const int tid = threadIdx.x, lane = tid & 31, wid = tid >> 5;
    const int wm = wid & 3, wn = wid >> 2;
    const int g = lane >> 2, tg = lane & 3;
    const int kBase = blockIdx.x * 1024;    // <<<64,256>>>

    {
        float c = g_c;
#pragma unroll
        for (int l = 0; l < 4; l++) vs[tid + l * 256] = g_v[kBase + tid + l * 256] + c;
    }

    const int mrow = lane & 7, mat = lane >> 3;
    uint32_t aBase[2], aX[2];
    const uint32_t aKs = (uint32_t)(mat >> 1);
#pragma unroll
    for (int mt = 0; mt < 2; mt++) {
        int r = wm * 32 + mt * 16 + (mat & 1) * 8 + mrow;
        aBase[mt] = (uint32_t)(r * 128);
        aX[mt] = (uint32_t)(r & 7);
    }
    uint32_t bBase[4], bX[4];
    const uint32_t bKs = (uint32_t)(mat & 1);
#pragma unroll
    for (int ntp = 0; ntp < 4; ntp++) {
        int n = wn * 64 + ntp * 16 + (mat >> 1) * 8 + mrow;
        bBase[ntp] = (uint32_t)(n * 128);
        bX[ntp] = (uint32_t)(n & 7);
    }

    float acc[2][8][4] = {};
    float tpart = 0.f;
    const int jrow = tid & 127;
    const uint32_t jswz = (uint32_t)(jrow & 7);

    auto load_stage = [&](int buf, int k0) {
        uint32_t sa = tilesU + buf * GTILE;
#pragma unroll
        for (int l = 0; l < 4; l++) {
            int idx = tid + l * 256;
            int r = idx >> 3, s = idx & 7;
            uint32_t so = (uint32_t)(r * 128 + ((s ^ (r & 7)) << 4));
            CP16(sa + so, g_Xt + (size_t)r * NROWS + kBase + k0 + s * 8);
        }
    };

    auto compute_stage = [&](int buf, int c) {
        uint32_t base = tilesU + buf * GTILE;
#pragma unroll
        for (uint32_t kk = 0; kk < 4; kk++) {
            uint32_t a[2][4];
#pragma unroll
            for (int mt = 0; mt < 2; mt++)
                LDSM4(a[mt], base + aBase[mt] + ((((kk << 1) | aKs) ^ aX[mt]) << 4));
#pragma unroll
            for (int ntp = 0; ntp < 4; ntp++) {
                uint32_t b[4];
                LDSM4(b, base + bBase[ntp] + ((((kk << 1) | bKs) ^ bX[ntp]) << 4));
#pragma unroll
                for (int h = 0; h < 2; h++) {
                    int nt = ntp * 2 + h;
                    MMA4(acc[0][nt], a[0][0], a[0][1], a[0][2], a[0][3],
                         b[h * 2], b[h * 2 + 1]);
                    MMA4(acc[1][nt], a[1][0], a[1][1], a[1][2], a[1][3],
                         b[h * 2], b[h * 2 + 1]);
                }
            }
        }
        if (tid < 128) {
            const float* vc = vs + c * GKC;
            const char* rowp = (const char*)(sm + 4096) + buf * GTILE + jrow * 128;
#pragma unroll
            for (int s = 0; s < 8; s++) {
                uint4 q = *(const uint4*)(rowp + (((uint32_t)s ^ jswz) << 4));
                const __half* hh = (const __half*)&q;
#pragma unroll
                for (int e = 0; e < 8; e++)
                    tpart += __half2float(hh[e]) * vc[s * 8 + e];
            }
        }
    };

    load_stage(0, 0);
    CP_COMMIT();
    load_stage(1, GKC);
    CP_COMMIT();

#pragma unroll 1
    for (int c = 0; c < 1024 / GKC; c++) {  // 16 chunks
        CP_WAIT1();
        __syncthreads();
        if (c + 2 < 1024 / GKC) load_stage((c + 2) % GNSTG, (c + 2) * GKC);
        CP_COMMIT();
        compute_stage(c % GNSTG, c);
    }

#pragma unroll
    for (int mt = 0; mt < 2; mt++)
#pragma unroll
        for (int nt = 0; nt < 8; nt++)
#pragma unroll
            for (int f = 0; f < 4; f++) {
                int i = wm * 32 + mt * 16 + g + (f >> 1) * 8;
                int j = wn * 64 + nt * 8 + tg * 2 + (f & 1);
                atomicAdd(&g_G[i * SDIM + j], acc[mt][nt][f]);
            }
    if (tid < 128) atomicAdd(&g_t[tid], tpart);
}

// ---------------------------------------------------------------------------
// Solve G y = t by Jacobi (12 iters), then w = w_struct - y.
// ---------------------------------------------------------------------------
__global__ void k_solve(const float* __restrict__ w_struct) {
    __shared__ float y[SDIM];
    __shared__ float tt[SDIM];
    int tid = threadIdx.x;  // 128 threads
    float dinv = 1.f / g_G[tid * SDIM + tid];
    tt[tid] = g_t[tid];
    y[tid] = tt[tid] * dinv;
    __syncthreads();
    for (int it = 0; it < 12; it++) {
        float s = 0.f;
#pragma unroll 8
        for (int m = 0; m < SDIM; m++) s += g_G[tid * SDIM + m] * y[m];
        float yn = y[tid] + (tt[tid] - s) * dinv;
        __syncthreads();
        y[tid] = yn;
        __syncthreads();
    }
    g_w[tid] = w_struct[tid] - y[tid];
}

// ---------------------------------------------------------------------------
// Final: out_i = v_i + c + X_i . w
// ---------------------------------------------------------------------------
__global__ __launch_bounds__(256)
void k_final(const float* __restrict__ X, float* __restrict__ out) {
    __shared__ float sw[SDIM];
    int tid = threadIdx.x;
    if (tid < SDIM) sw[tid] = g_w[tid];
    __syncthreads();
    float c = g_c;
    int lane = tid & 31;
    int warp = (blockIdx.x * blockDim.x + tid) >> 5;
    int nwarps = (gridDim.x * blockDim.x) >> 5;
    for (int row = warp; row < NROWS; row += nwarps) {
        const float* xr = &X[(size_t)row * SDIM];
        float s = xr[lane] * sw[lane] + xr[lane + 32] * sw[lane + 32] +
                  xr[lane + 64] * sw[lane + 64] + xr[lane + 96] * sw[lane + 96];
#pragma unroll
        for (int o = 16; o > 0; o >>= 1) s += __shfl_down_sync(0xffffffffu, s, o);
        if (lane == 0) out[row] = g_v[row] + c + s;
    }
}

// ---------------------------------------------------------------------------
extern "C" void kernel_launch(void* const* d_in, const int* in_sizes, int n_in,
                              void* d_out, int out_size) {
    const float* X        = (const float*)d_in[0];  // structured [N,128]
    const float* d1       = (const float*)d_in[1];  // [N,512]
    const float* W1       = (const float*)d_in[2];  // [512,1024]
    const float* b1       = (const float*)d_in[3];  // [1024]
    const float* W2       = (const float*)d_in[4];  // [1024,256]
    const float* b2       = (const float*)d_in[5];  // [256]
    const float* w_struct = (const float*)d_in[6];  // [128,1]
    const float* w_deep   = (const float*)d_in[7];  // [256,1]
    float* out = (float*)d_out;

    cudaFuncSetAttribute(k_mlp_mma, cudaFuncAttributeMaxDynamicSharedMemorySize,
                         SMEM_MMA);
    cudaFuncSetAttribute(k_gram_mma, cudaFuncAttributeMaxDynamicSharedMemorySize,
                         SMEM_GRAM);

    k_prep<<<2048, 256>>>(W1, W2, b2, w_deep);
    k_conv_Xt<<<dim3(NROWS / 32, SDIM / 32), dim3(32, 8)>>>(X);
    k_mlp_mma<<<dim3(HDIM / 128, NROWS / 128), 256, SMEM_MMA>>>(d1, b1);
    k_gram_mma<<<64, 256, SMEM_GRAM>>>();
    k_solve<<<1, SDIM>>>(w_struct);
    k_final<<<1024, 256>>>(X, out);
}